// round 2
// baseline (speedup 1.0000x reference)
#include <cuda_runtime.h>
#include <cuda_bf16.h>

// Problem constants (from reference setup_inputs)
#define BB 8
#define CC 64
#define OO 64
#define HH 80
#define WW 800

#define TW 128          // w-tile per CTA
#define THREADS 256
#define WK_STRIDE 68    // padded [c][o] weight stride (16B aligned, conflict-reduced)

// Dynamic SMEM layout:
//   s_xs : CC*TW floats        (gathered x tile, [c][ww])
//   s_wk : CC*WK_STRIDE floats (per-tap weight, [c][o], padded)
//   s_row: 3*TW ints
//   s_col: 3*TW ints
#define SMEM_FLOATS (CC*TW + CC*WK_STRIDE)
#define SMEM_BYTES  (SMEM_FLOATS*4 + 3*TW*4*2)

__global__ __launch_bounds__(THREADS)
void AdaptiveConv2d_kernel(const float* __restrict__ x,
                           const float* __restrict__ dh,
                           const float* __restrict__ dw,
                           const float* __restrict__ weight,
                           const float* __restrict__ bias,
                           float* __restrict__ out)
{
    extern __shared__ float smem[];
    float* s_xs = smem;                         // CC*TW
    float* s_wk = smem + CC*TW;                 // CC*WK_STRIDE
    int*   s_row = (int*)(s_wk + CC*WK_STRIDE); // 3*TW
    int*   s_col = s_row + 3*TW;                // 3*TW

    const int b  = blockIdx.z;
    const int h  = blockIdx.y;
    const int w0 = blockIdx.x * TW;
    const int tid = threadIdx.x;

    // ---- precompute gather indices for this (b, h, w-tile) ----
    if (tid < TW) {
        int w  = w0 + tid;
        int wc = (w < WW) ? w : (WW - 1);   // clamp for OOB lanes (never stored)
        int dilh = (int)dh[b*WW + wc]; if (dilh < 1) dilh = 1;
        int dilw = (int)dw[b*WW + wc]; if (dilw < 1) dilw = 1;

        int d = h - dilh; d = (d < 0) ? -d : d;
        s_row[0*TW + tid] = d % HH;                 // idxD
        s_row[1*TW + tid] = h;                      // center
        int up = h + dilh;
        s_row[2*TW + tid] = (up >= HH) ? h : up;    // idxU

        int l = wc - dilw; l = (l < 0) ? -l : l;
        s_col[0*TW + tid] = l % WW;                 // idxL
        s_col[1*TW + tid] = wc;                     // center
        int rt = wc + dilw;
        s_col[2*TW + tid] = (rt >= WW) ? (WW - 1 - (rt % WW)) : rt;  // idxR
    }

    // thread -> (o-block, w-block): 8 o-blocks x 32 w-blocks
    const int obk = tid >> 5;   // 0..7   -> o = obk*8 + oo
    const int wbk = tid & 31;   // 0..31  -> w = w0 + wbk*4 + j

    // accumulators: 8 o x 4 w, init with bias
    float acc[8][4];
#pragma unroll
    for (int oo = 0; oo < 8; ++oo) {
        float bv = bias[obk*8 + oo];
#pragma unroll
        for (int j = 0; j < 4; ++j) acc[oo][j] = bv;
    }

    const float* xb = x + (size_t)b * CC * HH * WW;
    const float4* xs4 = (const float4*)s_xs;
    const float4* wk4 = (const float4*)s_wk;

    for (int k = 0; k < 9; ++k) {
        const int ri = k / 3;   // row tap
        const int ci = k % 3;   // col tap

        __syncthreads();   // protect previous tap's SMEM

        // stage weight tap k, transposed to [c][o] with pad
        const float* wkg = weight + k * OO * CC;
        for (int idx = tid; idx < OO * CC; idx += THREADS) {
            int o = idx >> 6;
            int c = idx & 63;
            s_wk[c * WK_STRIDE + o] = wkg[idx];
        }

        // gather x tile [c][ww]
        const int* rrow = &s_row[ri * TW];
        const int* rcol = &s_col[ci * TW];
        for (int idx = tid; idx < CC * TW; idx += THREADS) {
            int c  = idx >> 7;      // TW == 128
            int ww = idx & 127;
            int r   = rrow[ww];
            int col = rcol[ww];
            s_xs[c * TW + ww] = xb[(c * HH + r) * WW + col];
        }

        __syncthreads();

        // compute: per c, 3x LDS.128 + 32 FFMA
#pragma unroll 4
        for (int c = 0; c < CC; ++c) {
            float4 xv = xs4[c * (TW/4) + wbk];
            float4 wa = wk4[c * (WK_STRIDE/4) + (obk << 1)];
            float4 wc4 = wk4[c * (WK_STRIDE/4) + (obk << 1) + 1];

            acc[0][0] += wa.x*xv.x; acc[0][1] += wa.x*xv.y; acc[0][2] += wa.x*xv.z; acc[0][3] += wa.x*xv.w;
            acc[1][0] += wa.y*xv.x; acc[1][1] += wa.y*xv.y; acc[1][2] += wa.y*xv.z; acc[1][3] += wa.y*xv.w;
            acc[2][0] += wa.z*xv.x; acc[2][1] += wa.z*xv.y; acc[2][2] += wa.z*xv.z; acc[2][3] += wa.z*xv.w;
            acc[3][0] += wa.w*xv.x; acc[3][1] += wa.w*xv.y; acc[3][2] += wa.w*xv.z; acc[3][3] += wa.w*xv.w;
            acc[4][0] += wc4.x*xv.x; acc[4][1] += wc4.x*xv.y; acc[4][2] += wc4.x*xv.z; acc[4][3] += wc4.x*xv.w;
            acc[5][0] += wc4.y*xv.x; acc[5][1] += wc4.y*xv.y; acc[5][2] += wc4.y*xv.z; acc[5][3] += wc4.y*xv.w;
            acc[6][0] += wc4.z*xv.x; acc[6][1] += wc4.z*xv.y; acc[6][2] += wc4.z*xv.z; acc[6][3] += wc4.z*xv.w;
            acc[7][0] += wc4.w*xv.x; acc[7][1] += wc4.w*xv.y; acc[7][2] += wc4.w*xv.z; acc[7][3] += wc4.w*xv.w;
        }
    }

    // ---- store ----
    const int w = w0 + wbk * 4;
    if (w < WW) {   // w is a multiple of 4 and WW%4==0, so full float4 is in-range
#pragma unroll
        for (int oo = 0; oo < 8; ++oo) {
            int o = obk * 8 + oo;
            size_t off = (((size_t)b * OO + o) * HH + h) * WW + w;
            float4 v = make_float4(acc[oo][0], acc[oo][1], acc[oo][2], acc[oo][3]);
            *(float4*)(out + off) = v;
        }
    }
}

extern "C" void kernel_launch(void* const* d_in, const int* in_sizes, int n_in,
                              void* d_out, int out_size)
{
    const float* x      = (const float*)d_in[0];
    const float* dh     = (const float*)d_in[1];
    const float* dw     = (const float*)d_in[2];
    const float* weight = (const float*)d_in[3];
    const float* bias   = (const float*)d_in[4];
    float* out = (float*)d_out;

    // 53,248 B dynamic SMEM (> 48 KB static limit) — opt in every call (idempotent)
    cudaFuncSetAttribute(AdaptiveConv2d_kernel,
                         cudaFuncAttributeMaxDynamicSharedMemorySize, SMEM_BYTES);

    dim3 grid((WW + TW - 1) / TW, HH, BB);   // 7 x 80 x 8
    AdaptiveConv2d_kernel<<<grid, THREADS, SMEM_BYTES>>>(x, dh, dw, weight, bias, out);
}

// round 7
// speedup vs baseline: 1.7475x; 1.7475x over previous
#include <cuda_runtime.h>
#include <cuda_bf16.h>
#include <cstdint>

// Problem constants
#define BB 8
#define CC 64
#define OO 64
#define HH 80
#define WW 800
#define TW 64            // w per CTA; M = 2 h-rows * 64 w = 128
#define THREADS 256

// Strip: per channel, 8 rows x 72 cols, fp32 (tf32-rounded)
#define S_COLS 72
#define S_ROWS 8
#define S_STRIDE 577     // floats per channel (576 + 1 pad, odd)

// SMEM layout (byte offsets)
#define OFF_TABLE 0                         // int[9*128] = 4608
#define OFF_WS    4608                      // two weight buffers, each 64*68*4 = 17408
#define WS_BYTES  17408
#define OFF_STRIP 39424                     // float[64*577] = 147712
#define SMEM_TOTAL (OFF_STRIP + CC*S_STRIDE*4)   // 187,136 B

#define EPI_STRIDE 132   // epilogue [o][m] float stride (reuses WS area: 64*132*4 = 33,792 <= 34,816)

// ---------------- helpers ----------------
static __device__ __forceinline__ float tf32r(float x) {
    uint32_t u;
    asm("cvt.rna.tf32.f32 %0, %1;" : "=r"(u) : "f"(x));
    return __uint_as_float(u);
}
static __device__ __forceinline__ void mma_tf32(float* c,
                                                uint32_t a0, uint32_t a1, uint32_t a2, uint32_t a3,
                                                uint32_t b0, uint32_t b1) {
    asm volatile(
        "mma.sync.aligned.m16n8k8.row.col.f32.tf32.tf32.f32 "
        "{%0,%1,%2,%3}, {%4,%5,%6,%7}, {%8,%9}, {%0,%1,%2,%3};"
        : "+f"(c[0]), "+f"(c[1]), "+f"(c[2]), "+f"(c[3])
        : "r"(a0), "r"(a1), "r"(a2), "r"(a3), "r"(b0), "r"(b1));
}

// ---------------- kernel ----------------
__global__ __launch_bounds__(THREADS, 1)
void AdaptiveConv2d_hmma_kernel(const float* __restrict__ x,
                                const float* __restrict__ dh,
                                const float* __restrict__ dw,
                                const float* __restrict__ weight,
                                const float* __restrict__ bias,
                                float* __restrict__ out)
{
    extern __shared__ __align__(16) char smc[];
    int*   s_table = (int*)(smc + OFF_TABLE);
    float* strip   = (float*)(smc + OFF_STRIP);

    const int tid  = threadIdx.x;
    const int lane = tid & 31;
    const int wid  = tid >> 5;
    const int lr   = lane >> 2;     // 0..7
    const int lc   = lane & 3;      // 0..3
    const int mw   = wid & 3;       // m-warp block (rows mw*32..+31)
    const int nw   = wid >> 2;      // n-warp block (cols nw*32..+31)

    const int b  = blockIdx.z;
    const int h0 = blockIdx.y * 2;
    const int w0 = blockIdx.x * TW;

    // ---- index table: base strip offset per (tap, m) ----
    if (tid < 128) {
        const int m = tid;
        const int hsel = m >> 6, wl = m & 63;
        const int h = h0 + hsel;
        int w = w0 + wl; if (w > WW - 1) w = WW - 1;
        int dilh = (int)dh[b * WW + w]; if (dilh < 1) dilh = 1;
        int dilw = (int)dw[b * WW + w]; if (dilw < 1) dilw = 1;

        int rows[3], cols[3];
        int d = h - dilh; rows[0] = (d < 0) ? -d : d;              // |h-dil| < H
        rows[1] = h;
        int up = h + dilh; rows[2] = (up < HH) ? up : h;
        int l = w - dilw; cols[0] = (l < 0) ? -l : l;              // |w-dil| < W
        cols[1] = w;
        int rt = w + dilw; cols[2] = (rt < WW) ? rt : (2 * WW - 1 - rt);

#pragma unroll
        for (int ri = 0; ri < 3; ++ri)
#pragma unroll
            for (int ci = 0; ci < 3; ++ci)
                s_table[(ri * 3 + ci) * 128 + m] =
                    (rows[ri] - (h0 - 3)) * S_COLS + (cols[ci] - (w0 - 4));
    }

    // ---- strip: x[b, c, h0-3..h0+4, w0-4..w0+67], tf32-rounded fp32 ----
    {
        const float* xb = x + (size_t)b * CC * HH * WW;
        for (int idx = tid; idx < CC * S_ROWS * 18; idx += THREADS) {
            int c   = idx / (S_ROWS * 18);
            int rem = idx - c * (S_ROWS * 18);
            int r   = rem / 18;
            int j4  = rem - r * 18;
            int gr = h0 - 3 + r; gr = (gr < 0) ? 0 : ((gr > HH - 1) ? HH - 1 : gr);
            int gc = w0 - 4 + j4 * 4; gc = (gc < 0) ? 0 : ((gc > WW - 4) ? WW - 4 : gc);
            const float4 v = *(const float4*)&xb[((size_t)c * HH + gr) * WW + gc];
            float* d0 = &strip[c * S_STRIDE + r * S_COLS + j4 * 4];
            d0[0] = tf32r(v.x); d0[1] = tf32r(v.y); d0[2] = tf32r(v.z); d0[3] = tf32r(v.w);
        }
    }
    // ---- stage weight tap 0 into buffer 0 ----
    {
        float* ws0 = (float*)(smc + OFF_WS);
        const float4* wg4 = (const float4*)weight;
#pragma unroll
        for (int i = 0; i < 4; ++i) {
            float4 f = wg4[tid + 256 * i];
            int e0 = (tid + 256 * i) * 4;
            int o = e0 >> 6, c = e0 & 63;
            float4 g = make_float4(tf32r(f.x), tf32r(f.y), tf32r(f.z), tf32r(f.w));
            *(float4*)(ws0 + o * 68 + c) = g;
        }
    }
    __syncthreads();

    // ---- accumulators: [mt 0..1][nt 0..3][4] ----
    float acc[2][4][4];
#pragma unroll
    for (int mt = 0; mt < 2; ++mt)
#pragma unroll
        for (int nt = 0; nt < 4; ++nt)
#pragma unroll
            for (int j = 0; j < 4; ++j) acc[mt][nt][j] = 0.0f;

    // ---- tap loop ----
    for (int t = 0; t < 9; ++t) {
        // prefetch next tap weights to registers
        float4 wreg[4];
        if (t + 1 < 9) {
            const float4* wg4 = (const float4*)(weight + (size_t)(t + 1) * OO * CC);
#pragma unroll
            for (int i = 0; i < 4; ++i) wreg[i] = wg4[tid + 256 * i];
        }

        // per-thread row bases (4 rows this thread touches in A frags)
        int bs0[2], bs1[2];
#pragma unroll
        for (int mt = 0; mt < 2; ++mt) {
            bs0[mt] = s_table[t * 128 + mw * 32 + mt * 16 + lr];
            bs1[mt] = s_table[t * 128 + mw * 32 + mt * 16 + lr + 8];
        }

        const uint32_t* sA = (const uint32_t*)strip + lc * S_STRIDE;
        const uint32_t* sB = (const uint32_t*)(smc + OFF_WS + (t & 1) * WS_BYTES)
                             + (nw * 32 + lr) * 68 + lc;

#pragma unroll
        for (int k0 = 0; k0 < 8; ++k0) {
            uint32_t b0[4], b1[4];
#pragma unroll
            for (int nt = 0; nt < 4; ++nt) {
                b0[nt] = sB[nt * 544];          // 8*68
                b1[nt] = sB[nt * 544 + 4];
            }
#pragma unroll
            for (int mt = 0; mt < 2; ++mt) {
                uint32_t a0 = sA[bs0[mt]];
                uint32_t a1 = sA[bs1[mt]];
                uint32_t a2 = sA[bs0[mt] + 4 * S_STRIDE];
                uint32_t a3 = sA[bs1[mt] + 4 * S_STRIDE];
#pragma unroll
                for (int nt = 0; nt < 4; ++nt)
                    mma_tf32(acc[mt][nt], a0, a1, a2, a3, b0[nt], b1[nt]);
            }
            sA += 8 * S_STRIDE;
            sB += 8;
        }

        // stage prefetched weights into the other buffer
        if (t + 1 < 9) {
            float* wn = (float*)(smc + OFF_WS + ((t + 1) & 1) * WS_BYTES);
#pragma unroll
            for (int i = 0; i < 4; ++i) {
                int e0 = (tid + 256 * i) * 4;
                int o = e0 >> 6, c = e0 & 63;
                float4 f = wreg[i];
                float4 g = make_float4(tf32r(f.x), tf32r(f.y), tf32r(f.z), tf32r(f.w));
                *(float4*)(wn + o * 68 + c) = g;
            }
        }
        __syncthreads();
    }

    // ---- epilogue: frags -> smem [o][m] -> coalesced global (+bias) ----
    float* epi = (float*)(smc + OFF_WS);   // reuse weight area
#pragma unroll
    for (int mt = 0; mt < 2; ++mt) {
#pragma unroll
        for (int nt = 0; nt < 4; ++nt) {
            int m0 = mw * 32 + mt * 16 + lr;
            int o0 = nw * 32 + nt * 8 + 2 * lc;
            epi[(o0    ) * EPI_STRIDE + m0    ] = acc[mt][nt][0];
            epi[(o0 + 1) * EPI_STRIDE + m0    ] = acc[mt][nt][1];
            epi[(o0    ) * EPI_STRIDE + m0 + 8] = acc[mt][nt][2];
            epi[(o0 + 1) * EPI_STRIDE + m0 + 8] = acc[mt][nt][3];
        }
    }
    __syncthreads();

    for (int idx = tid; idx < OO * 128; idx += THREADS) {
        int o = idx >> 7, m = idx & 127;
        int w = w0 + (m & 63);
        int h = h0 + (m >> 6);
        if (w < WW)
            out[(((size_t)b * OO + o) * HH + h) * WW + w] =
                epi[o * EPI_STRIDE + m] + __ldg(&bias[o]);
    }
}

extern "C" void kernel_launch(void* const* d_in, const int* in_sizes, int n_in,
                              void* d_out, int out_size)
{
    const float* x      = (const float*)d_in[0];
    const float* dh     = (const float*)d_in[1];
    const float* dw     = (const float*)d_in[2];
    const float* weight = (const float*)d_in[3];
    const float* bias   = (const float*)d_in[4];
    float* out = (float*)d_out;

    cudaFuncSetAttribute(AdaptiveConv2d_hmma_kernel,
                         cudaFuncAttributeMaxDynamicSharedMemorySize, SMEM_TOTAL);

    dim3 grid((WW + TW - 1) / TW, HH / 2, BB);   // 13 x 40 x 8 = 4160
    AdaptiveConv2d_hmma_kernel<<<grid, THREADS, SMEM_TOTAL>>>(x, dh, dw, weight, bias, out);
}

// round 8
// speedup vs baseline: 2.0314x; 1.1625x over previous
#include <cuda_runtime.h>
#include <cuda_bf16.h>
#include <cstdint>

// Problem constants
#define BB 8
#define CC 64
#define OO 64
#define HH 80
#define WW 800
#define TW 64            // w per CTA; M = 2 h-rows * 64 w = 128
#define THREADS 256

// Strip: per channel, 8 rows x 72 cols, fp32 (tf32-rounded)
#define S_COLS 72
#define S_ROWS 8
#define S_STRIDE 584     // floats per channel; 584 mod 32 == 8 -> lc*8 bank spread,
                         // conflict-free A-fragment gathers (lr-consecutive bases)

// SMEM layout (byte offsets)
#define OFF_TABLE 0                         // int[9*128] = 4608
#define OFF_WS    4608                      // two weight buffers, each 64*68*4 = 17408
#define WS_BYTES  17408
#define OFF_STRIP 39424                     // float[64*584] = 149504
#define SMEM_TOTAL (OFF_STRIP + CC*S_STRIDE*4)   // 188,928 B

#define EPI_STRIDE 132   // epilogue [o][m] float stride (reuses WS area: 64*132*4 = 33,792)

// ---------------- helpers ----------------
static __device__ __forceinline__ float tf32r(float x) {
    uint32_t u;
    asm("cvt.rna.tf32.f32 %0, %1;" : "=r"(u) : "f"(x));
    return __uint_as_float(u);
}
static __device__ __forceinline__ void mma_tf32(float* c,
                                                uint32_t a0, uint32_t a1, uint32_t a2, uint32_t a3,
                                                uint32_t b0, uint32_t b1) {
    asm volatile(
        "mma.sync.aligned.m16n8k8.row.col.f32.tf32.tf32.f32 "
        "{%0,%1,%2,%3}, {%4,%5,%6,%7}, {%8,%9}, {%0,%1,%2,%3};"
        : "+f"(c[0]), "+f"(c[1]), "+f"(c[2]), "+f"(c[3])
        : "r"(a0), "r"(a1), "r"(a2), "r"(a3), "r"(b0), "r"(b1));
}

// ---------------- kernel ----------------
__global__ __launch_bounds__(THREADS, 1)
void AdaptiveConv2d_hmma_kernel(const float* __restrict__ x,
                                const float* __restrict__ dh,
                                const float* __restrict__ dw,
                                const float* __restrict__ weight,
                                const float* __restrict__ bias,
                                float* __restrict__ out)
{
    extern __shared__ __align__(16) char smc[];
    int*   s_table = (int*)(smc + OFF_TABLE);
    float* strip   = (float*)(smc + OFF_STRIP);

    const int tid  = threadIdx.x;
    const int lane = tid & 31;
    const int wid  = tid >> 5;
    const int lr   = lane >> 2;     // 0..7
    const int lc   = lane & 3;      // 0..3
    const int mw   = wid & 3;       // m-warp block (rows mw*32..+31)
    const int nw   = wid >> 2;      // n-warp block (cols nw*32..+31)

    const int b  = blockIdx.z;
    const int h0 = blockIdx.y * 2;
    const int w0 = blockIdx.x * TW;

    // ---- index table: base strip offset per (tap, m) ----
    if (tid < 128) {
        const int m = tid;
        const int hsel = m >> 6, wl = m & 63;
        const int h = h0 + hsel;
        int w = w0 + wl; if (w > WW - 1) w = WW - 1;
        int dilh = (int)dh[b * WW + w]; if (dilh < 1) dilh = 1;
        int dilw = (int)dw[b * WW + w]; if (dilw < 1) dilw = 1;

        int rows[3], cols[3];
        int d = h - dilh; rows[0] = (d < 0) ? -d : d;              // |h-dil| < H
        rows[1] = h;
        int up = h + dilh; rows[2] = (up < HH) ? up : h;
        int l = w - dilw; cols[0] = (l < 0) ? -l : l;              // |w-dil| < W
        cols[1] = w;
        int rt = w + dilw; cols[2] = (rt < WW) ? rt : (2 * WW - 1 - rt);

#pragma unroll
        for (int ri = 0; ri < 3; ++ri)
#pragma unroll
            for (int ci = 0; ci < 3; ++ci)
                s_table[(ri * 3 + ci) * 128 + m] =
                    (rows[ri] - (h0 - 3)) * S_COLS + (cols[ci] - (w0 - 4));
    }

    // ---- strip: x[b, c, h0-3..h0+4, w0-4..w0+67], tf32-rounded fp32 ----
    {
        const float* xb = x + (size_t)b * CC * HH * WW;
        for (int idx = tid; idx < CC * S_ROWS * 18; idx += THREADS) {
            int c   = idx / (S_ROWS * 18);
            int rem = idx - c * (S_ROWS * 18);
            int r   = rem / 18;
            int j4  = rem - r * 18;
            int gr = h0 - 3 + r; gr = (gr < 0) ? 0 : ((gr > HH - 1) ? HH - 1 : gr);
            int gc = w0 - 4 + j4 * 4; gc = (gc < 0) ? 0 : ((gc > WW - 4) ? WW - 4 : gc);
            const float4 v = *(const float4*)&xb[((size_t)c * HH + gr) * WW + gc];
            float* d0 = &strip[c * S_STRIDE + r * S_COLS + j4 * 4];
            d0[0] = tf32r(v.x); d0[1] = tf32r(v.y); d0[2] = tf32r(v.z); d0[3] = tf32r(v.w);
        }
    }
    // ---- stage weight tap 0 into buffer 0 ----
    {
        float* ws0 = (float*)(smc + OFF_WS);
        const float4* wg4 = (const float4*)weight;
#pragma unroll
        for (int i = 0; i < 4; ++i) {
            float4 f = wg4[tid + 256 * i];
            int e0 = (tid + 256 * i) * 4;
            int o = e0 >> 6, c = e0 & 63;
            float4 g = make_float4(tf32r(f.x), tf32r(f.y), tf32r(f.z), tf32r(f.w));
            *(float4*)(ws0 + o * 68 + c) = g;
        }
    }
    __syncthreads();

    // ---- accumulators: [mt 0..1][nt 0..3][4] ----
    float acc[2][4][4];
#pragma unroll
    for (int mt = 0; mt < 2; ++mt)
#pragma unroll
        for (int nt = 0; nt < 4; ++nt)
#pragma unroll
            for (int j = 0; j < 4; ++j) acc[mt][nt][j] = 0.0f;

    // ---- tap loop ----
    for (int t = 0; t < 9; ++t) {
        // prefetch next tap weights to registers
        float4 wreg[4];
        if (t + 1 < 9) {
            const float4* wg4 = (const float4*)(weight + (size_t)(t + 1) * OO * CC);
#pragma unroll
            for (int i = 0; i < 4; ++i) wreg[i] = wg4[tid + 256 * i];
        }

        // per-thread row bases (4 rows this thread touches in A frags)
        int bs0[2], bs1[2];
#pragma unroll
        for (int mt = 0; mt < 2; ++mt) {
            bs0[mt] = s_table[t * 128 + mw * 32 + mt * 16 + lr];
            bs1[mt] = s_table[t * 128 + mw * 32 + mt * 16 + lr + 8];
        }

        const uint32_t* sA = (const uint32_t*)strip + lc * S_STRIDE;
        const uint32_t* sB = (const uint32_t*)(smc + OFF_WS + (t & 1) * WS_BYTES)
                             + (nw * 32 + lr) * 68 + lc;

#pragma unroll
        for (int k0 = 0; k0 < 8; ++k0) {
            uint32_t b0[4], b1[4];
#pragma unroll
            for (int nt = 0; nt < 4; ++nt) {
                b0[nt] = sB[nt * 544];          // 8*68
                b1[nt] = sB[nt * 544 + 4];
            }
#pragma unroll
            for (int mt = 0; mt < 2; ++mt) {
                uint32_t a0 = sA[bs0[mt]];
                uint32_t a1 = sA[bs1[mt]];
                uint32_t a2 = sA[bs0[mt] + 4 * S_STRIDE];
                uint32_t a3 = sA[bs1[mt] + 4 * S_STRIDE];
#pragma unroll
                for (int nt = 0; nt < 4; ++nt)
                    mma_tf32(acc[mt][nt], a0, a1, a2, a3, b0[nt], b1[nt]);
            }
            sA += 8 * S_STRIDE;
            sB += 8;
        }

        // stage prefetched weights into the other buffer
        if (t + 1 < 9) {
            float* wn = (float*)(smc + OFF_WS + ((t + 1) & 1) * WS_BYTES);
#pragma unroll
            for (int i = 0; i < 4; ++i) {
                int e0 = (tid + 256 * i) * 4;
                int o = e0 >> 6, c = e0 & 63;
                float4 f = wreg[i];
                float4 g = make_float4(tf32r(f.x), tf32r(f.y), tf32r(f.z), tf32r(f.w));
                *(float4*)(wn + o * 68 + c) = g;
            }
        }
        __syncthreads();
    }

    // ---- epilogue: frags -> smem [o][m] -> coalesced global (+bias) ----
    float* epi = (float*)(smc + OFF_WS);   // reuse weight area
#pragma unroll
    for (int mt = 0; mt < 2; ++mt) {
#pragma unroll
        for (int nt = 0; nt < 4; ++nt) {
            int m0 = mw * 32 + mt * 16 + lr;
            int o0 = nw * 32 + nt * 8 + 2 * lc;
            epi[(o0    ) * EPI_STRIDE + m0    ] = acc[mt][nt][0];
            epi[(o0 + 1) * EPI_STRIDE + m0    ] = acc[mt][nt][1];
            epi[(o0    ) * EPI_STRIDE + m0 + 8] = acc[mt][nt][2];
            epi[(o0 + 1) * EPI_STRIDE + m0 + 8] = acc[mt][nt][3];
        }
    }
    __syncthreads();

    for (int idx = tid; idx < OO * 128; idx += THREADS) {
        int o = idx >> 7, m = idx & 127;
        int w = w0 + (m & 63);
        int h = h0 + (m >> 6);
        if (w < WW)
            out[(((size_t)b * OO + o) * HH + h) * WW + w] =
                epi[o * EPI_STRIDE + m] + __ldg(&bias[o]);
    }
}

extern "C" void kernel_launch(void* const* d_in, const int* in_sizes, int n_in,
                              void* d_out, int out_size)
{
    const float* x      = (const float*)d_in[0];
    const float* dh     = (const float*)d_in[1];
    const float* dw     = (const float*)d_in[2];
    const float* weight = (const float*)d_in[3];
    const float* bias   = (const float*)d_in[4];
    float* out = (float*)d_out;

    cudaFuncSetAttribute(AdaptiveConv2d_hmma_kernel,
                         cudaFuncAttributeMaxDynamicSharedMemorySize, SMEM_TOTAL);

    dim3 grid((WW + TW - 1) / TW, HH / 2, BB);   // 13 x 40 x 8 = 4160
    AdaptiveConv2d_hmma_kernel<<<grid, THREADS, SMEM_TOTAL>>>(x, dh, dw, weight, bias, out);
}

// round 9
// speedup vs baseline: 2.4245x; 1.1935x over previous
#include <cuda_runtime.h>
#include <cuda_bf16.h>
#include <cstdint>

// Problem constants
#define BB 8
#define CC 64
#define OO 64
#define HH 80
#define WW 800
#define TW 64            // w per CTA; M = 2 h-rows * 64 w = 128
#define THREADS 256
#define CHALF 32         // channels per K-split pass

// Strip: per channel, 8 rows x 72 cols, fp32 (tf32-rounded); only CHALF channels resident
#define S_COLS 72
#define S_ROWS 8
#define S_STRIDE 584     // floats per channel; 584 mod 32 == 8 -> conflict-free A gathers

// Weight stage: [o=64][c=32] padded to stride 36 (36 mod 32 == 4 -> conflict-free B reads)
#define WS_STRIDE 36
#define WS_BYTES  (OO*WS_STRIDE*4)          // 9216

// SMEM layout (byte offsets)
#define OFF_TABLE 0                          // int[9*128] = 4608
#define OFF_WS    4608                       // two weight buffers = 18432
#define OFF_STRIP 23040                      // float[32*584] = 74752
#define SMEM_TOTAL (OFF_STRIP + CHALF*S_STRIDE*4)   // 97,792 B -> 2 CTAs/SM

#define EPI_STRIDE 132   // epilogue [o][m]; reuses strip area (33,792 B <= 74,752)

// ---------------- helpers ----------------
static __device__ __forceinline__ float tf32r(float x) {
    uint32_t u;
    asm("cvt.rna.tf32.f32 %0, %1;" : "=r"(u) : "f"(x));
    return __uint_as_float(u);
}
static __device__ __forceinline__ void mma_tf32(float* c,
                                                uint32_t a0, uint32_t a1, uint32_t a2, uint32_t a3,
                                                uint32_t b0, uint32_t b1) {
    asm volatile(
        "mma.sync.aligned.m16n8k8.row.col.f32.tf32.tf32.f32 "
        "{%0,%1,%2,%3}, {%4,%5,%6,%7}, {%8,%9}, {%0,%1,%2,%3};"
        : "+f"(c[0]), "+f"(c[1]), "+f"(c[2]), "+f"(c[3])
        : "r"(a0), "r"(a1), "r"(a2), "r"(a3), "r"(b0), "r"(b1));
}

// ---------------- kernel ----------------
__global__ __launch_bounds__(THREADS, 2)
void AdaptiveConv2d_hmma_kernel(const float* __restrict__ x,
                                const float* __restrict__ dh,
                                const float* __restrict__ dw,
                                const float* __restrict__ weight,
                                const float* __restrict__ bias,
                                float* __restrict__ out)
{
    extern __shared__ __align__(16) char smc[];
    int*   s_table = (int*)(smc + OFF_TABLE);
    float* strip   = (float*)(smc + OFF_STRIP);

    const int tid  = threadIdx.x;
    const int lane = tid & 31;
    const int wid  = tid >> 5;
    const int lr   = lane >> 2;     // 0..7
    const int lc   = lane & 3;      // 0..3
    const int mw   = wid & 3;       // m-warp block (rows mw*32..+31)
    const int nw   = wid >> 2;      // n-warp block (cols nw*32..+31)

    const int b  = blockIdx.z;
    const int h0 = blockIdx.y * 2;
    const int w0 = blockIdx.x * TW;

    // ---- index table: base strip offset per (tap, m) ----
    if (tid < 128) {
        const int m = tid;
        const int hsel = m >> 6, wl = m & 63;
        const int h = h0 + hsel;
        int w = w0 + wl; if (w > WW - 1) w = WW - 1;
        int dilh = (int)dh[b * WW + w]; if (dilh < 1) dilh = 1;
        int dilw = (int)dw[b * WW + w]; if (dilw < 1) dilw = 1;

        int rows[3], cols[3];
        int d = h - dilh; rows[0] = (d < 0) ? -d : d;              // |h-dil| < H
        rows[1] = h;
        int up = h + dilh; rows[2] = (up < HH) ? up : h;
        int l = w - dilw; cols[0] = (l < 0) ? -l : l;              // |w-dil| < W
        cols[1] = w;
        int rt = w + dilw; cols[2] = (rt < WW) ? rt : (2 * WW - 1 - rt);

#pragma unroll
        for (int ri = 0; ri < 3; ++ri)
#pragma unroll
            for (int ci = 0; ci < 3; ++ci)
                s_table[(ri * 3 + ci) * 128 + m] =
                    (rows[ri] - (h0 - 3)) * S_COLS + (cols[ci] - (w0 - 4));
    }

    // ---- strip loader for one 32-channel half ----
    const float* xb = x + (size_t)b * CC * HH * WW;
    auto load_strip = [&](int half) {
        const float* xh = xb + (size_t)half * CHALF * HH * WW;
        for (int idx = tid; idx < CHALF * S_ROWS * 18; idx += THREADS) {
            int c   = idx / (S_ROWS * 18);
            int rem = idx - c * (S_ROWS * 18);
            int r   = rem / 18;
            int j4  = rem - r * 18;
            int gr = h0 - 3 + r; gr = (gr < 0) ? 0 : ((gr > HH - 1) ? HH - 1 : gr);
            int gc = w0 - 4 + j4 * 4; gc = (gc < 0) ? 0 : ((gc > WW - 4) ? WW - 4 : gc);
            const float4 v = *(const float4*)&xh[((size_t)c * HH + gr) * WW + gc];
            float* d0 = &strip[c * S_STRIDE + r * S_COLS + j4 * 4];
            d0[0] = tf32r(v.x); d0[1] = tf32r(v.y); d0[2] = tf32r(v.z); d0[3] = tf32r(v.w);
        }
    };

    // ---- stage 0 (half 0, tap 0) weights into buffer 0; strip half 0 ----
    {
        float* ws0 = (float*)(smc + OFF_WS);
#pragma unroll
        for (int i = 0; i < 2; ++i) {
            int idx = tid + 256 * i;            // 0..511
            int o = idx >> 3, c4 = (idx & 7) * 4;
            float4 f = *(const float4*)(weight + (size_t)o * CC + c4);
            float4 g = make_float4(tf32r(f.x), tf32r(f.y), tf32r(f.z), tf32r(f.w));
            *(float4*)(ws0 + o * WS_STRIDE + c4) = g;
        }
    }
    load_strip(0);
    __syncthreads();

    // ---- accumulators: [mt 0..1][nt 0..3][4] ----
    float acc[2][4][4];
#pragma unroll
    for (int mt = 0; mt < 2; ++mt)
#pragma unroll
        for (int nt = 0; nt < 4; ++nt)
#pragma unroll
            for (int j = 0; j < 4; ++j) acc[mt][nt][j] = 0.0f;

    // ---- 18 stages: half-major, tap-minor ----
    int stage = 0;
    for (int half = 0; half < 2; ++half) {
        if (half == 1) {
            load_strip(1);      // previous stage's trailing __syncthreads covered old reads
            __syncthreads();
        }
        for (int t = 0; t < 9; ++t, ++stage) {
            // prefetch next stage's weights to registers
            float4 wreg[2];
            int o_pf = 0, c4_pf = 0;
            if (stage + 1 < 18) {
                int tn = (t + 1 == 9) ? 0 : (t + 1);
                int hn = (t + 1 == 9) ? 1 : half;
                const float* wg = weight + (size_t)tn * OO * CC + hn * CHALF;
#pragma unroll
                for (int i = 0; i < 2; ++i) {
                    int idx = tid + 256 * i;
                    int o = idx >> 3, c4 = (idx & 7) * 4;
                    wreg[i] = *(const float4*)(wg + (size_t)o * CC + c4);
                }
            }

            // per-thread A row bases
            int bs0[2], bs1[2];
#pragma unroll
            for (int mt = 0; mt < 2; ++mt) {
                bs0[mt] = s_table[t * 128 + mw * 32 + mt * 16 + lr];
                bs1[mt] = s_table[t * 128 + mw * 32 + mt * 16 + lr + 8];
            }

            const uint32_t* sA = (const uint32_t*)strip + lc * S_STRIDE;
            const uint32_t* sB = (const uint32_t*)(smc + OFF_WS + (stage & 1) * WS_BYTES)
                                 + (nw * 32 + lr) * WS_STRIDE + lc;

#pragma unroll
            for (int k0 = 0; k0 < 4; ++k0) {
                uint32_t b0[4], b1[4];
#pragma unroll
                for (int nt = 0; nt < 4; ++nt) {
                    b0[nt] = sB[nt * (8 * WS_STRIDE)];
                    b1[nt] = sB[nt * (8 * WS_STRIDE) + 4];
                }
#pragma unroll
                for (int mt = 0; mt < 2; ++mt) {
                    uint32_t a0 = sA[bs0[mt]];
                    uint32_t a1 = sA[bs1[mt]];
                    uint32_t a2 = sA[bs0[mt] + 4 * S_STRIDE];
                    uint32_t a3 = sA[bs1[mt] + 4 * S_STRIDE];
#pragma unroll
                    for (int nt = 0; nt < 4; ++nt)
                        mma_tf32(acc[mt][nt], a0, a1, a2, a3, b0[nt], b1[nt]);
                }
                sA += 8 * S_STRIDE;
                sB += 8;
            }

            // store prefetched weights into the other buffer
            if (stage + 1 < 18) {
                float* wn = (float*)(smc + OFF_WS + ((stage + 1) & 1) * WS_BYTES);
#pragma unroll
                for (int i = 0; i < 2; ++i) {
                    int idx = tid + 256 * i;
                    int o = idx >> 3, c4 = (idx & 7) * 4;
                    float4 f = wreg[i];
                    float4 g = make_float4(tf32r(f.x), tf32r(f.y), tf32r(f.z), tf32r(f.w));
                    *(float4*)(wn + o * WS_STRIDE + c4) = g;
                }
            }
            __syncthreads();
        }
    }

    // ---- epilogue: frags -> smem [o][m] (strip area) -> coalesced global (+bias) ----
    float* epi = (float*)(smc + OFF_STRIP);
#pragma unroll
    for (int mt = 0; mt < 2; ++mt) {
#pragma unroll
        for (int nt = 0; nt < 4; ++nt) {
            int m0 = mw * 32 + mt * 16 + lr;
            int o0 = nw * 32 + nt * 8 + 2 * lc;
            epi[(o0    ) * EPI_STRIDE + m0    ] = acc[mt][nt][0];
            epi[(o0 + 1) * EPI_STRIDE + m0    ] = acc[mt][nt][1];
            epi[(o0    ) * EPI_STRIDE + m0 + 8] = acc[mt][nt][2];
            epi[(o0 + 1) * EPI_STRIDE + m0 + 8] = acc[mt][nt][3];
        }
    }
    __syncthreads();

    for (int idx = tid; idx < OO * 128; idx += THREADS) {
        int o = idx >> 7, m = idx & 127;
        int w = w0 + (m & 63);
        int h = h0 + (m >> 6);
        if (w < WW)
            out[(((size_t)b * OO + o) * HH + h) * WW + w] =
                epi[o * EPI_STRIDE + m] + __ldg(&bias[o]);
    }
}

extern "C" void kernel_launch(void* const* d_in, const int* in_sizes, int n_in,
                              void* d_out, int out_size)
{
    const float* x      = (const float*)d_in[0];
    const float* dh     = (const float*)d_in[1];
    const float* dw     = (const float*)d_in[2];
    const float* weight = (const float*)d_in[3];
    const float* bias   = (const float*)d_in[4];
    float* out = (float*)d_out;

    cudaFuncSetAttribute(AdaptiveConv2d_hmma_kernel,
                         cudaFuncAttributeMaxDynamicSharedMemorySize, SMEM_TOTAL);

    dim3 grid((WW + TW - 1) / TW, HH / 2, BB);   // 13 x 40 x 8 = 4160
    AdaptiveConv2d_hmma_kernel<<<grid, THREADS, SMEM_TOTAL>>>(x, dh, dw, weight, bias, out);
}

// round 10
// speedup vs baseline: 2.6382x; 1.0881x over previous
#include <cuda_runtime.h>
#include <cuda_bf16.h>
#include <cstdint>

// Problem constants
#define BB 8
#define CC 64
#define OO 64
#define HH 80
#define WW 800
#define TW 64            // w per CTA; M = 2 h-rows * 64 w = 128
#define THREADS 256
#define CHALF 16         // channels per K-split pass (4 passes)
#define NHALF 4

// Strip: per channel, 8 rows x 72 cols, fp32 (tf32-rounded); CHALF channels resident
#define S_COLS 72
#define S_ROWS 8
#define S_STRIDE 580     // floats per channel; 580 mod 32 == 4 -> A bank = 8*lc + bs (tiled)

// Weight stage: [o=64][c=16] padded to stride 24 (24 mod 32 -> perfect LDS.64 bank tiling)
#define WS_STRIDE 24
#define WS_BYTES  (OO*WS_STRIDE*4)          // 6144

// SMEM layout (byte offsets)
#define OFF_TABLE 0                          // int[9*128] = 4608
#define OFF_WS    4608                       // two weight buffers = 12288
#define OFF_STRIP 16896                      // float[16*580] = 37120
#define SMEM_TOTAL (OFF_STRIP + CHALF*S_STRIDE*4)   // 54,016 B -> 3 CTAs/SM

#define EPI_STRIDE 132   // epilogue [o][m]; reuses strip area (33,792 B <= 37,120)

// ---------------- helpers ----------------
static __device__ __forceinline__ float tf32r(float x) {
    uint32_t u;
    asm("cvt.rna.tf32.f32 %0, %1;" : "=r"(u) : "f"(x));
    return __uint_as_float(u);
}
static __device__ __forceinline__ void mma_tf32(float* c,
                                                uint32_t a0, uint32_t a1, uint32_t a2, uint32_t a3,
                                                uint32_t b0, uint32_t b1) {
    asm volatile(
        "mma.sync.aligned.m16n8k8.row.col.f32.tf32.tf32.f32 "
        "{%0,%1,%2,%3}, {%4,%5,%6,%7}, {%8,%9}, {%0,%1,%2,%3};"
        : "+f"(c[0]), "+f"(c[1]), "+f"(c[2]), "+f"(c[3])
        : "r"(a0), "r"(a1), "r"(a2), "r"(a3), "r"(b0), "r"(b1));
}

// ---------------- kernel ----------------
__global__ __launch_bounds__(THREADS, 3)
void AdaptiveConv2d_hmma_kernel(const float* __restrict__ x,
                                const float* __restrict__ dh,
                                const float* __restrict__ dw,
                                const float* __restrict__ weight,
                                const float* __restrict__ bias,
                                float* __restrict__ out)
{
    extern __shared__ __align__(16) char smc[];
    int*   s_table = (int*)(smc + OFF_TABLE);
    float* strip   = (float*)(smc + OFF_STRIP);

    const int tid  = threadIdx.x;
    const int lane = tid & 31;
    const int wid  = tid >> 5;
    const int lr   = lane >> 2;     // 0..7
    const int lc   = lane & 3;      // 0..3
    const int mw   = wid & 3;       // m-warp block (rows mw*32..+31)
    const int nw   = wid >> 2;      // n-warp block (cols nw*32..+31)

    const int b  = blockIdx.z;
    const int h0 = blockIdx.y * 2;
    const int w0 = blockIdx.x * TW;

    // ---- index table: base strip position per (tap, m) ----
    if (tid < 128) {
        const int m = tid;
        const int hsel = m >> 6, wl = m & 63;
        const int h = h0 + hsel;
        int w = w0 + wl; if (w > WW - 1) w = WW - 1;
        int dilh = (int)dh[b * WW + w]; if (dilh < 1) dilh = 1;
        int dilw = (int)dw[b * WW + w]; if (dilw < 1) dilw = 1;

        int rows[3], cols[3];
        int d = h - dilh; rows[0] = (d < 0) ? -d : d;              // |h-dil| < H
        rows[1] = h;
        int up = h + dilh; rows[2] = (up < HH) ? up : h;
        int l = w - dilw; cols[0] = (l < 0) ? -l : l;              // |w-dil| < W
        cols[1] = w;
        int rt = w + dilw; cols[2] = (rt < WW) ? rt : (2 * WW - 1 - rt);

#pragma unroll
        for (int ri = 0; ri < 3; ++ri)
#pragma unroll
            for (int ci = 0; ci < 3; ++ci)
                s_table[(ri * 3 + ci) * 128 + m] =
                    (rows[ri] - (h0 - 3)) * S_COLS + (cols[ci] - (w0 - 4));
    }

    // ---- strip loader for one 16-channel quarter ----
    const float* xb = x + (size_t)b * CC * HH * WW;
    auto load_strip = [&](int half) {
        const float* xh = xb + (size_t)half * CHALF * HH * WW;
        for (int idx = tid; idx < CHALF * S_ROWS * 18; idx += THREADS) {
            int c   = idx / (S_ROWS * 18);
            int rem = idx - c * (S_ROWS * 18);
            int r   = rem / 18;
            int j4  = rem - r * 18;
            int gr = h0 - 3 + r; gr = (gr < 0) ? 0 : ((gr > HH - 1) ? HH - 1 : gr);
            int gc = w0 - 4 + j4 * 4; gc = (gc < 0) ? 0 : ((gc > WW - 4) ? WW - 4 : gc);
            const float4 v = *(const float4*)&xh[((size_t)c * HH + gr) * WW + gc];
            float4 g = make_float4(tf32r(v.x), tf32r(v.y), tf32r(v.z), tf32r(v.w));
            *(float4*)&strip[c * S_STRIDE + r * S_COLS + j4 * 4] = g;
        }
    };

    // weight staging indices: each thread stores one float4
    const int wo  = tid >> 2;            // 0..63
    const int wc4 = (tid & 3) * 4;       // 0,4,8,12

    // ---- stage 0 (half 0, tap 0) weights into buffer 0 ----
    {
        float4 f = *(const float4*)(weight + (size_t)wo * CC + wc4);
        float4 g = make_float4(tf32r(f.x), tf32r(f.y), tf32r(f.z), tf32r(f.w));
        *(float4*)((float*)(smc + OFF_WS) + wo * WS_STRIDE + wc4) = g;
    }

    // ---- accumulators: [mt 0..1][nt 0..3][4] ----
    float acc[2][4][4];
#pragma unroll
    for (int mt = 0; mt < 2; ++mt)
#pragma unroll
        for (int nt = 0; nt < 4; ++nt)
#pragma unroll
            for (int j = 0; j < 4; ++j) acc[mt][nt][j] = 0.0f;

    // ---- 36 stages: half-major (4 halves), tap-minor (9 taps) ----
    int stage = 0;
    for (int half = 0; half < NHALF; ++half) {
        load_strip(half);       // prior stage's trailing sync covers old strip reads
        __syncthreads();
        for (int t = 0; t < 9; ++t, ++stage) {
            // prefetch next stage's weights (one float4 per thread)
            float4 wreg;
            if (stage + 1 < 9 * NHALF) {
                int tn = (t + 1 == 9) ? 0 : (t + 1);
                int hn = (t + 1 == 9) ? half + 1 : half;
                wreg = *(const float4*)(weight + (size_t)tn * OO * CC
                                        + (size_t)wo * CC + hn * CHALF + wc4);
            }

            // per-thread A row bases
            int bs0[2], bs1[2];
#pragma unroll
            for (int mt = 0; mt < 2; ++mt) {
                bs0[mt] = s_table[t * 128 + mw * 32 + mt * 16 + lr];
                bs1[mt] = s_table[t * 128 + mw * 32 + mt * 16 + lr + 8];
            }

            // k-slot permutation: slot lc <-> channel 2lc, slot lc+4 <-> channel 2lc+1
            const uint32_t* sA = (const uint32_t*)strip + (2 * lc) * S_STRIDE;
            const float*    sB = (const float*)(smc + OFF_WS + (stage & 1) * WS_BYTES)
                                 + (nw * 32 + lr) * WS_STRIDE + 2 * lc;

#pragma unroll
            for (int kg = 0; kg < 2; ++kg) {
                uint32_t b0[4], b1[4];
#pragma unroll
                for (int nt = 0; nt < 4; ++nt) {
                    float2 f = *(const float2*)(sB + nt * (8 * WS_STRIDE) + kg * 8);
                    b0[nt] = __float_as_uint(f.x);
                    b1[nt] = __float_as_uint(f.y);
                }
#pragma unroll
                for (int mt = 0; mt < 2; ++mt) {
                    const uint32_t* sAk = sA + kg * 8 * S_STRIDE;
                    uint32_t a0 = sAk[bs0[mt]];
                    uint32_t a1 = sAk[bs1[mt]];
                    uint32_t a2 = sAk[S_STRIDE + bs0[mt]];
                    uint32_t a3 = sAk[S_STRIDE + bs1[mt]];
#pragma unroll
                    for (int nt = 0; nt < 4; ++nt)
                        mma_tf32(acc[mt][nt], a0, a1, a2, a3, b0[nt], b1[nt]);
                }
            }

            // store prefetched weights into the other buffer
            if (stage + 1 < 9 * NHALF) {
                float4 g = make_float4(tf32r(wreg.x), tf32r(wreg.y), tf32r(wreg.z), tf32r(wreg.w));
                *(float4*)((float*)(smc + OFF_WS + ((stage + 1) & 1) * WS_BYTES)
                           + wo * WS_STRIDE + wc4) = g;
            }
            __syncthreads();
        }
    }

    // ---- epilogue: frags -> smem [o][m] (strip area) -> coalesced global (+bias) ----
    float* epi = (float*)(smc + OFF_STRIP);
#pragma unroll
    for (int mt = 0; mt < 2; ++mt) {
#pragma unroll
        for (int nt = 0; nt < 4; ++nt) {
            int m0 = mw * 32 + mt * 16 + lr;
            int o0 = nw * 32 + nt * 8 + 2 * lc;
            epi[(o0    ) * EPI_STRIDE + m0    ] = acc[mt][nt][0];
            epi[(o0 + 1) * EPI_STRIDE + m0    ] = acc[mt][nt][1];
            epi[(o0    ) * EPI_STRIDE + m0 + 8] = acc[mt][nt][2];
            epi[(o0 + 1) * EPI_STRIDE + m0 + 8] = acc[mt][nt][3];
        }
    }
    __syncthreads();

    for (int idx = tid; idx < OO * 128; idx += THREADS) {
        int o = idx >> 7, m = idx & 127;
        int w = w0 + (m & 63);
        int h = h0 + (m >> 6);
        if (w < WW)
            out[(((size_t)b * OO + o) * HH + h) * WW + w] =
                epi[o * EPI_STRIDE + m] + __ldg(&bias[o]);
    }
}

extern "C" void kernel_launch(void* const* d_in, const int* in_sizes, int n_in,
                              void* d_out, int out_size)
{
    const float* x      = (const float*)d_in[0];
    const float* dh     = (const float*)d_in[1];
    const float* dw     = (const float*)d_in[2];
    const float* weight = (const float*)d_in[3];
    const float* bias   = (const float*)d_in[4];
    float* out = (float*)d_out;

    cudaFuncSetAttribute(AdaptiveConv2d_hmma_kernel,
                         cudaFuncAttributeMaxDynamicSharedMemorySize, SMEM_TOTAL);

    dim3 grid((WW + TW - 1) / TW, HH / 2, BB);   // 13 x 40 x 8 = 4160
    AdaptiveConv2d_hmma_kernel<<<grid, THREADS, SMEM_TOTAL>>>(x, dh, dw, weight, bias, out);
}

// round 12
// speedup vs baseline: 3.1296x; 1.1863x over previous
#include <cuda_runtime.h>
#include <cuda_bf16.h>
#include <cstdint>

// Problem constants
#define BB 8
#define CC 64
#define OO 64
#define HH 80
#define WW 800
#define TW 64            // w per CTA
#define HROWS 4          // h-rows per CTA; M = 4*64 = 256
#define THREADS 256
#define CHALF 16         // channels per K-split pass
#define NHALF 4

// Strip: per channel, 10 rows x 72 cols, fp32 (tf32-rounded); CHALF channels resident
#define S_COLS 72
#define S_ROWS 10
#define S_STRIDE 740     // floats per channel (720 + 20 pad); 740 mod 32 == 4 -> A bank = 8*lc + bs

// Weight stage: [o=64][c=16] stride 24 (LDS.64 conflict-free per half-warp phase)
#define WS_STRIDE 24
#define WS_BYTES  (OO*WS_STRIDE*4)          // 6144

// SMEM layout (byte offsets)
#define OFF_TABLE 0                          // int[9*256] = 9216
#define OFF_WS    9216                       // two weight buffers = 12288
#define OFF_STRIP 21504                      // float[16*740] = 47360
#define SMEM_TOTAL (OFF_STRIP + CHALF*S_STRIDE*4)   // 68,864 B -> 2 CTAs/SM

#define EPI_STRIDE 132   // epilogue [o][m-chunk of 128]; 64*132*4 = 33,792 <= 47,360

// ---------------- helpers ----------------
static __device__ __forceinline__ float tf32r(float x) {
    uint32_t u;
    asm("cvt.rna.tf32.f32 %0, %1;" : "=r"(u) : "f"(x));
    return __uint_as_float(u);
}
static __device__ __forceinline__ void mma_tf32(float* c,
                                                uint32_t a0, uint32_t a1, uint32_t a2, uint32_t a3,
                                                uint32_t b0, uint32_t b1) {
    asm volatile(
        "mma.sync.aligned.m16n8k8.row.col.f32.tf32.tf32.f32 "
        "{%0,%1,%2,%3}, {%4,%5,%6,%7}, {%8,%9}, {%0,%1,%2,%3};"
        : "+f"(c[0]), "+f"(c[1]), "+f"(c[2]), "+f"(c[3])
        : "r"(a0), "r"(a1), "r"(a2), "r"(a3), "r"(b0), "r"(b1));
}

// ---------------- kernel ----------------
__global__ __launch_bounds__(THREADS, 2)
void AdaptiveConv2d_hmma_kernel(const float* __restrict__ x,
                                const float* __restrict__ dh,
                                const float* __restrict__ dw,
                                const float* __restrict__ weight,
                                const float* __restrict__ bias,
                                float* __restrict__ out)
{
    extern __shared__ __align__(16) char smc[];
    int*   s_table = (int*)(smc + OFF_TABLE);
    float* strip   = (float*)(smc + OFF_STRIP);

    const int tid  = threadIdx.x;
    const int lane = tid & 31;
    const int wid  = tid >> 5;
    const int lr   = lane >> 2;     // 0..7
    const int lc   = lane & 3;      // 0..3
    const int mw   = wid & 3;       // m-warp block: rows mw*64..+63 (one h-row)
    const int nw   = wid >> 2;      // n-warp block: cols nw*32..+31

    const int b  = blockIdx.z;
    const int h0 = blockIdx.y * HROWS;
    const int w0 = blockIdx.x * TW;

    // ---- index table: base strip position per (tap, m), m = hsel*64 + wl ----
    {
        const int m = tid;                 // 0..255
        const int hsel = m >> 6, wl = m & 63;
        const int h = h0 + hsel;
        int w = w0 + wl; if (w > WW - 1) w = WW - 1;
        int dilh = (int)dh[b * WW + w]; if (dilh < 1) dilh = 1;
        int dilw = (int)dw[b * WW + w]; if (dilw < 1) dilw = 1;

        int rows[3], cols[3];
        int d = h - dilh; rows[0] = (d < 0) ? -d : d;              // |h-dil| < H
        rows[1] = h;
        int up = h + dilh; rows[2] = (up < HH) ? up : h;
        int l = w - dilw; cols[0] = (l < 0) ? -l : l;              // |w-dil| < W
        cols[1] = w;
        int rt = w + dilw; cols[2] = (rt < WW) ? rt : (2 * WW - 1 - rt);

#pragma unroll
        for (int ri = 0; ri < 3; ++ri)
#pragma unroll
            for (int ci = 0; ci < 3; ++ci)
                s_table[(ri * 3 + ci) * 256 + m] =
                    (rows[ri] - (h0 - 3)) * S_COLS + (cols[ci] - (w0 - 4));
    }

    // ---- strip loader for one 16-channel quarter (10-row window) ----
    const float* xb = x + (size_t)b * CC * HH * WW;
    auto load_strip = [&](int half) {
        const float* xh = xb + (size_t)half * CHALF * HH * WW;
        for (int idx = tid; idx < CHALF * S_ROWS * 18; idx += THREADS) {
            int c   = idx / (S_ROWS * 18);
            int rem = idx - c * (S_ROWS * 18);
            int r   = rem / 18;
            int j4  = rem - r * 18;
            int gr = h0 - 3 + r; gr = (gr < 0) ? 0 : ((gr > HH - 1) ? HH - 1 : gr);
            int gc = w0 - 4 + j4 * 4; gc = (gc < 0) ? 0 : ((gc > WW - 4) ? WW - 4 : gc);
            const float4 v = *(const float4*)&xh[((size_t)c * HH + gr) * WW + gc];
            float4 g = make_float4(tf32r(v.x), tf32r(v.y), tf32r(v.z), tf32r(v.w));
            *(float4*)&strip[c * S_STRIDE + r * S_COLS + j4 * 4] = g;
        }
    };

    // weight staging indices: each thread stores one float4
    const int wo  = tid >> 2;            // 0..63
    const int wc4 = (tid & 3) * 4;       // 0,4,8,12

    // ---- stage 0 (half 0, tap 0) weights into buffer 0 ----
    {
        float4 f = *(const float4*)(weight + (size_t)wo * CC + wc4);
        float4 g = make_float4(tf32r(f.x), tf32r(f.y), tf32r(f.z), tf32r(f.w));
        *(float4*)((float*)(smc + OFF_WS) + wo * WS_STRIDE + wc4) = g;
    }

    // ---- accumulators: [mt 0..3][nt 0..3][4] ----
    float acc[4][4][4];
#pragma unroll
    for (int mt = 0; mt < 4; ++mt)
#pragma unroll
        for (int nt = 0; nt < 4; ++nt)
#pragma unroll
            for (int j = 0; j < 4; ++j) acc[mt][nt][j] = 0.0f;

    // ---- 36 stages: half-major (4 halves), tap-minor (9 taps) ----
    int stage = 0;
    for (int half = 0; half < NHALF; ++half) {
        load_strip(half);       // prior stage's trailing sync covers old strip reads
        __syncthreads();
        for (int t = 0; t < 9; ++t, ++stage) {
            // prefetch next stage's weights (one float4 per thread)
            float4 wreg;
            if (stage + 1 < 9 * NHALF) {
                const int tn = (t + 1 == 9) ? 0 : (t + 1);
                const int hn = (t + 1 == 9) ? half + 1 : half;
                wreg = *(const float4*)(weight + (size_t)tn * OO * CC
                                        + (size_t)wo * CC + hn * CHALF + wc4);
            }

            // per-thread A row bases: rows mw*64 + mt*16 + lr (+8)
            int bs0[4], bs1[4];
#pragma unroll
            for (int mt = 0; mt < 4; ++mt) {
                const int m0 = mw * 64 + mt * 16 + lr;
                bs0[mt] = s_table[t * 256 + m0];
                bs1[mt] = s_table[t * 256 + m0 + 8];
            }

            // k-slot permutation: slot lc <-> channel 8kg+2lc, slot lc+4 <-> 8kg+2lc+1
            const uint32_t* sA = (const uint32_t*)strip + (2 * lc) * S_STRIDE;
            const float*    sB = (const float*)(smc + OFF_WS + (stage & 1) * WS_BYTES)
                                 + (nw * 32 + lr) * WS_STRIDE + 2 * lc;

#pragma unroll
            for (int kg = 0; kg < 2; ++kg) {
                uint32_t b0[4], b1[4];
#pragma unroll
                for (int nt = 0; nt < 4; ++nt) {
                    const float2 f = *(const float2*)(sB + nt * (8 * WS_STRIDE) + kg * 8);
                    b0[nt] = __float_as_uint(f.x);
                    b1[nt] = __float_as_uint(f.y);
                }
                const uint32_t* sAk = sA + kg * 8 * S_STRIDE;
#pragma unroll
                for (int mt = 0; mt < 4; ++mt) {
                    const uint32_t a0 = sAk[bs0[mt]];
                    const uint32_t a1 = sAk[bs1[mt]];
                    const uint32_t a2 = sAk[S_STRIDE + bs0[mt]];
                    const uint32_t a3 = sAk[S_STRIDE + bs1[mt]];
#pragma unroll
                    for (int nt = 0; nt < 4; ++nt)
                        mma_tf32(acc[mt][nt], a0, a1, a2, a3, b0[nt], b1[nt]);
                }
            }

            // store prefetched weights into the other buffer
            if (stage + 1 < 9 * NHALF) {
                const float4 g = make_float4(tf32r(wreg.x), tf32r(wreg.y),
                                             tf32r(wreg.z), tf32r(wreg.w));
                *(float4*)((float*)(smc + OFF_WS + ((stage + 1) & 1) * WS_BYTES)
                           + wo * WS_STRIDE + wc4) = g;
            }
            __syncthreads();
        }
    }

    // ---- epilogue: two 128-row chunks through smem [o][m'] (strip area) ----
    float* epi = (float*)(smc + OFF_STRIP);
    for (int ch = 0; ch < 2; ++ch) {
        __syncthreads();
        if ((mw >> 1) == ch) {          // warps owning m in [ch*128, ch*128+128)
#pragma unroll
            for (int mt = 0; mt < 4; ++mt) {
#pragma unroll
                for (int nt = 0; nt < 4; ++nt) {
                    const int m0 = (mw & 1) * 64 + mt * 16 + lr;
                    const int o0 = nw * 32 + nt * 8 + 2 * lc;
                    epi[(o0    ) * EPI_STRIDE + m0    ] = acc[mt][nt][0];
                    epi[(o0 + 1) * EPI_STRIDE + m0    ] = acc[mt][nt][1];
                    epi[(o0    ) * EPI_STRIDE + m0 + 8] = acc[mt][nt][2];
                    epi[(o0 + 1) * EPI_STRIDE + m0 + 8] = acc[mt][nt][3];
                }
            }
        }
        __syncthreads();
        for (int idx = tid; idx < OO * 128; idx += THREADS) {
            const int o = idx >> 7, mm = idx & 127;
            const int gm = ch * 128 + mm;
            const int w = w0 + (gm & 63);
            const int h = h0 + (gm >> 6);
            if (w < WW)
                out[(((size_t)b * OO + o) * HH + h) * WW + w] =
                    epi[o * EPI_STRIDE + mm] + __ldg(&bias[o]);
        }
    }
}

extern "C" void kernel_launch(void* const* d_in, const int* in_sizes, int n_in,
                              void* d_out, int out_size)
{
    const float* x      = (const float*)d_in[0];
    const float* dh     = (const float*)d_in[1];
    const float* dw     = (const float*)d_in[2];
    const float* weight = (const float*)d_in[3];
    const float* bias   = (const float*)d_in[4];
    float* out = (float*)d_out;

    cudaFuncSetAttribute(AdaptiveConv2d_hmma_kernel,
                         cudaFuncAttributeMaxDynamicSharedMemorySize, SMEM_TOTAL);

    dim3 grid((WW + TW - 1) / TW, HH / HROWS, BB);   // 13 x 20 x 8 = 2080
    AdaptiveConv2d_hmma_kernel<<<grid, THREADS, SMEM_TOTAL>>>(x, dh, dw, weight, bias, out);
}

// round 13
// speedup vs baseline: 4.6614x; 1.4894x over previous
#include <cuda_runtime.h>
#include <cuda_fp16.h>
#include <cstdint>

// Problem constants
#define BB 8
#define CC 64
#define OO 64
#define HH 80
#define WW 800
#define TW 64            // w per CTA
#define HROWS 4          // h-rows per CTA; M = 4*64 = 256
#define THREADS 256
#define CHALF 32         // channels per K-split pass (2 passes)
#define NHALF 2
#define NPAIR 16         // half2 channel-pairs resident per pass

// Strip: per channel-PAIR, 10 rows x 72 cols of half2 words
#define S_COLS 72
#define S_ROWS 10
#define PSTRIDE 744      // words per pair (720 + pad); 744 mod 32 == 8 -> A bank = 8*lc + bs (proven)

// Weight stage: half2 [o=64][pair=16] stride 20 words -> B banks (20*lr+lc) all distinct
#define WSTRIDE 20
#define WS_BYTES (OO*WSTRIDE*4)             // 5120

// SMEM layout (byte offsets)
#define OFF_TABLE 0                          // int[9*256] = 9216
#define OFF_WS    9216                       // two weight buffers = 10240
#define OFF_STRIP 19456                      // u32[16*744] = 47616
#define SMEM_TOTAL (OFF_STRIP + NPAIR*PSTRIDE*4)   // 67,072 B -> 2 CTAs/SM

#define EPI_STRIDE 132   // epilogue [o][m-chunk of 128]; 33,792 <= 47,616

// ---------------- helpers ----------------
static __device__ __forceinline__ void mma_f16(float* c,
                                               uint32_t a0, uint32_t a1, uint32_t a2, uint32_t a3,
                                               uint32_t b0, uint32_t b1) {
    asm volatile(
        "mma.sync.aligned.m16n8k16.row.col.f32.f16.f16.f32 "
        "{%0,%1,%2,%3}, {%4,%5,%6,%7}, {%8,%9}, {%0,%1,%2,%3};"
        : "+f"(c[0]), "+f"(c[1]), "+f"(c[2]), "+f"(c[3])
        : "r"(a0), "r"(a1), "r"(a2), "r"(a3), "r"(b0), "r"(b1));
}
static __device__ __forceinline__ uint32_t pack_h2(float lo, float hi) {
    __half2 h = __floats2half2_rn(lo, hi);   // .x = lo half (k even), .y = hi (k odd)
    return *(uint32_t*)&h;
}

// ---------------- kernel ----------------
__global__ __launch_bounds__(THREADS, 2)
void AdaptiveConv2d_hmma_kernel(const float* __restrict__ x,
                                const float* __restrict__ dh,
                                const float* __restrict__ dw,
                                const float* __restrict__ weight,
                                const float* __restrict__ bias,
                                float* __restrict__ out)
{
    extern __shared__ __align__(16) char smc[];
    int*      s_table = (int*)(smc + OFF_TABLE);
    uint32_t* strip   = (uint32_t*)(smc + OFF_STRIP);

    const int tid  = threadIdx.x;
    const int lane = tid & 31;
    const int wid  = tid >> 5;
    const int lr   = lane >> 2;     // 0..7
    const int lc   = lane & 3;      // 0..3
    const int mw   = wid & 3;       // m-warp block: rows mw*64..+63 (one h-row)
    const int nw   = wid >> 2;      // n-warp block: cols nw*32..+31

    const int b  = blockIdx.z;
    const int h0 = blockIdx.y * HROWS;
    const int w0 = blockIdx.x * TW;

    // ---- index table: base strip position per (tap, m), m = hsel*64 + wl ----
    {
        const int m = tid;                 // 0..255
        const int hsel = m >> 6, wl = m & 63;
        const int h = h0 + hsel;
        int w = w0 + wl; if (w > WW - 1) w = WW - 1;
        int dilh = (int)dh[b * WW + w]; if (dilh < 1) dilh = 1;
        int dilw = (int)dw[b * WW + w]; if (dilw < 1) dilw = 1;

        int rows[3], cols[3];
        int d = h - dilh; rows[0] = (d < 0) ? -d : d;              // |h-dil| < H
        rows[1] = h;
        int up = h + dilh; rows[2] = (up < HH) ? up : h;
        int l = w - dilw; cols[0] = (l < 0) ? -l : l;              // |w-dil| < W
        cols[1] = w;
        int rt = w + dilw; cols[2] = (rt < WW) ? rt : (2 * WW - 1 - rt);

#pragma unroll
        for (int ri = 0; ri < 3; ++ri)
#pragma unroll
            for (int ci = 0; ci < 3; ++ci)
                s_table[(ri * 3 + ci) * 256 + m] =
                    (rows[ri] - (h0 - 3)) * S_COLS + (cols[ci] - (w0 - 4));
    }

    // ---- strip loader: 16 channel-pairs of one half, packed half2 ----
    const float* xb = x + (size_t)b * CC * HH * WW;
    auto load_strip = [&](int half) {
        const float* xh = xb + (size_t)half * CHALF * HH * WW;
        for (int idx = tid; idx < NPAIR * S_ROWS * 18; idx += THREADS) {
            int p   = idx / (S_ROWS * 18);
            int rem = idx - p * (S_ROWS * 18);
            int r   = rem / 18;
            int j4  = rem - r * 18;
            int gr = h0 - 3 + r; gr = (gr < 0) ? 0 : ((gr > HH - 1) ? HH - 1 : gr);
            int gc = w0 - 4 + j4 * 4; gc = (gc < 0) ? 0 : ((gc > WW - 4) ? WW - 4 : gc);
            const size_t off = (size_t)(2 * p) * HH * WW + (size_t)gr * WW + gc;
            const float4 v0 = *(const float4*)&xh[off];
            const float4 v1 = *(const float4*)&xh[off + (size_t)HH * WW];
            uint4 g;
            g.x = pack_h2(v0.x, v1.x);
            g.y = pack_h2(v0.y, v1.y);
            g.z = pack_h2(v0.z, v1.z);
            g.w = pack_h2(v0.w, v1.w);
            *(uint4*)&strip[p * PSTRIDE + r * S_COLS + j4 * 4] = g;
        }
    };

    // weight staging: thread handles o = tid>>2, pairs wpr..wpr+3 (channels 2wpr..2wpr+7)
    const int wo  = tid >> 2;            // 0..63
    const int wpr = (tid & 3) * 4;       // 0,4,8,12

    auto stage_weights = [&](int t, int half, int buf) {
        const float* wg = weight + (size_t)t * OO * CC + (size_t)wo * CC + half * CHALF + 2 * wpr;
        const float4 f0 = *(const float4*)(wg);
        const float4 f1 = *(const float4*)(wg + 4);
        uint4 g;
        g.x = pack_h2(f0.x, f0.y);
        g.y = pack_h2(f0.z, f0.w);
        g.z = pack_h2(f1.x, f1.y);
        g.w = pack_h2(f1.z, f1.w);
        *(uint4*)((uint32_t*)(smc + OFF_WS + buf * WS_BYTES) + wo * WSTRIDE + wpr) = g;
    };

    // ---- stage 0 (half 0, tap 0) weights into buffer 0; strip half 0 ----
    stage_weights(0, 0, 0);
    load_strip(0);
    __syncthreads();

    // ---- accumulators: [mt 0..3][nt 0..3][4] ----
    float acc[4][4][4];
#pragma unroll
    for (int mt = 0; mt < 4; ++mt)
#pragma unroll
        for (int nt = 0; nt < 4; ++nt)
#pragma unroll
            for (int j = 0; j < 4; ++j) acc[mt][nt][j] = 0.0f;

    // ---- 18 stages: half-major (2 halves), tap-minor (9 taps) ----
    int stage = 0;
    for (int half = 0; half < NHALF; ++half) {
        if (half) {
            load_strip(half);   // prior stage's trailing sync covers old strip reads
            __syncthreads();
        }
        for (int t = 0; t < 9; ++t, ++stage) {
            // prefetch next stage's weights to registers
            float4 wf0, wf1;
            if (stage + 1 < 9 * NHALF) {
                const int tn = (t + 1 == 9) ? 0 : (t + 1);
                const int hn = (t + 1 == 9) ? half + 1 : half;
                const float* wg = weight + (size_t)tn * OO * CC
                                  + (size_t)wo * CC + hn * CHALF + 2 * wpr;
                wf0 = *(const float4*)(wg);
                wf1 = *(const float4*)(wg + 4);
            }

            // per-thread A row bases: rows mw*64 + mt*16 + lr (+8)
            int bs0[4], bs1[4];
#pragma unroll
            for (int mt = 0; mt < 4; ++mt) {
                const int m0 = mw * 64 + mt * 16 + lr;
                bs0[mt] = s_table[t * 256 + m0];
                bs1[mt] = s_table[t * 256 + m0 + 8];
            }

            const uint32_t* ws = (const uint32_t*)(smc + OFF_WS + (stage & 1) * WS_BYTES);
            const uint32_t* sB = ws + (nw * 32 + lr) * WSTRIDE + lc;

            // two k16 groups per stage (ki = 16-channel chunk)
#pragma unroll
            for (int ki = 0; ki < 2; ++ki) {
                uint32_t b0[4], b1[4];
#pragma unroll
                for (int nt = 0; nt < 4; ++nt) {
                    b0[nt] = sB[nt * (8 * WSTRIDE) + 8 * ki];
                    b1[nt] = sB[nt * (8 * WSTRIDE) + 8 * ki + 4];
                }
                const uint32_t* pA0 = strip + (8 * ki + lc) * PSTRIDE;
                const uint32_t* pA1 = pA0 + 4 * PSTRIDE;
#pragma unroll
                for (int mt = 0; mt < 4; ++mt) {
                    const uint32_t a0 = pA0[bs0[mt]];
                    const uint32_t a1 = pA0[bs1[mt]];
                    const uint32_t a2 = pA1[bs0[mt]];
                    const uint32_t a3 = pA1[bs1[mt]];
#pragma unroll
                    for (int nt = 0; nt < 4; ++nt)
                        mma_f16(acc[mt][nt], a0, a1, a2, a3, b0[nt], b1[nt]);
                }
            }

            // store prefetched weights into the other buffer
            if (stage + 1 < 9 * NHALF) {
                uint4 g;
                g.x = pack_h2(wf0.x, wf0.y);
                g.y = pack_h2(wf0.z, wf0.w);
                g.z = pack_h2(wf1.x, wf1.y);
                g.w = pack_h2(wf1.z, wf1.w);
                *(uint4*)((uint32_t*)(smc + OFF_WS + ((stage + 1) & 1) * WS_BYTES)
                          + wo * WSTRIDE + wpr) = g;
            }
            __syncthreads();
        }
    }

    // ---- epilogue: two 128-row chunks through smem [o][m'] (strip area) ----
    float* epi = (float*)(smc + OFF_STRIP);
    for (int ch = 0; ch < 2; ++ch) {
        __syncthreads();
        if ((mw >> 1) == ch) {          // warps owning m in [ch*128, ch*128+128)
#pragma unroll
            for (int mt = 0; mt < 4; ++mt) {
#pragma unroll
                for (int nt = 0; nt < 4; ++nt) {
                    const int m0 = (mw & 1) * 64 + mt * 16 + lr;
                    const int o0 = nw * 32 + nt * 8 + 2 * lc;
                    epi[(o0    ) * EPI_STRIDE + m0    ] = acc[mt][nt][0];
                    epi[(o0 + 1) * EPI_STRIDE + m0    ] = acc[mt][nt][1];
                    epi[(o0    ) * EPI_STRIDE + m0 + 8] = acc[mt][nt][2];
                    epi[(o0 + 1) * EPI_STRIDE + m0 + 8] = acc[mt][nt][3];
                }
            }
        }
        __syncthreads();
        for (int idx = tid; idx < OO * 128; idx += THREADS) {
            const int o = idx >> 7, mm = idx & 127;
            const int gm = ch * 128 + mm;
            const int w = w0 + (gm & 63);
            const int h = h0 + (gm >> 6);
            if (w < WW)
                out[(((size_t)b * OO + o) * HH + h) * WW + w] =
                    epi[o * EPI_STRIDE + mm] + __ldg(&bias[o]);
        }
    }
}

extern "C" void kernel_launch(void* const* d_in, const int* in_sizes, int n_in,
                              void* d_out, int out_size)
{
    const float* x      = (const float*)d_in[0];
    const float* dh     = (const float*)d_in[1];
    const float* dw     = (const float*)d_in[2];
    const float* weight = (const float*)d_in[3];
    const float* bias   = (const float*)d_in[4];
    float* out = (float*)d_out;

    cudaFuncSetAttribute(AdaptiveConv2d_hmma_kernel,
                         cudaFuncAttributeMaxDynamicSharedMemorySize, SMEM_TOTAL);

    dim3 grid((WW + TW - 1) / TW, HH / HROWS, BB);   // 13 x 20 x 8 = 2080
    AdaptiveConv2d_hmma_kernel<<<grid, THREADS, SMEM_TOTAL>>>(x, dh, dw, weight, bias, out);
}